// round 7
// baseline (speedup 1.0000x reference)
#include <cuda_runtime.h>
#include <cuda_fp16.h>

#define NNODES 50000
#define NEDGES 1600000
#define DIM 64
#define REP 4         // privatized counter replicas per node (contention 32 -> 8)
#define CAPR 32       // slots per replica; per-replica load ~Poisson(8), P(>32)~1e-11
#define NPB 40        // nodes per block in node_kernel (50000 = 1250 * 40)

// Scratch (allocation-free rule: __device__ globals)
__device__ uint4  d_g2h[NNODES * 8];          // per-node message, fp16x8 per entry [N,64]
__device__ float  d_hsum[NNODES * DIM];       // h_x + h_mu  [N,64]
__device__ float  d_v[3 * DIM];               // v1 | v2 | v3
__device__ float  d_Sw[NNODES * REP];         // partial edge-weight sums
__device__ int    d_cnt[NNODES * REP];        // per-(node,replica) cursors
__device__ int    d_rec[NNODES * REP * CAPR]; // dst index per (src, replica, slot)

// ---------------------------------------------------------------------------
// Kernel A: v1 = W4a*relu(W1), v2 = W4a*relu(-W1), v3 = W4b*relu(W2).
// ---------------------------------------------------------------------------
__global__ void prep_v_kernel(const float* __restrict__ W1,
                              const float* __restrict__ W2,
                              const float* __restrict__ W4) {
    int o = threadIdx.x;  // 0..63
    float a = 0.f, b = 0.f, c = 0.f;
#pragma unroll
    for (int j = 0; j < DIM; j++) {
        float w4a = W4[o * 192 + j];
        float w4b = W4[o * 192 + 64 + j];
        float w1 = W1[j], w2 = W2[j];
        a += w4a * fmaxf(w1, 0.f);
        b += w4a * fmaxf(-w1, 0.f);
        c += w4b * fmaxf(w2, 0.f);
    }
    d_v[o] = a;
    d_v[64 + o] = b;
    d_v[128 + o] = c;
}

// ---------------------------------------------------------------------------
// Kernel B: per-node precompute (two 64x64 GEMVs per node).
// Weights in SMEM stride-68 rows: conflict-free STS and LDS.128.
// g2 stored fp16. Also zeroes the REP cursors / Sw partials.
// ---------------------------------------------------------------------------
__global__ __launch_bounds__(256) void node_kernel(
    const float* __restrict__ mu, const float* __restrict__ x,
    const float* __restrict__ W1, const float* __restrict__ W3,
    const float* __restrict__ W4) {
    __shared__ float W3s[DIM * 68];    // W3s[o*68+k] = W3[o][k]
    __shared__ float W4cs[DIM * 68];   // W4cs[o*68+k] = W4[o][128+k]
    __shared__ float mus[NPB * DIM];
    __shared__ float hb[2][4 * DIM];
    __shared__ float W1s[DIM], v1s[DIM], v2s[DIM], xs[NPB];

    int tid = threadIdx.x;
    for (int i = tid; i < DIM * DIM; i += 256) {
        int o = i >> 6, k = i & 63;
        W3s[o * 68 + k]  = W3[i];
        W4cs[o * 68 + k] = W4[o * 192 + 128 + k];
    }
    if (tid < DIM) {
        W1s[tid] = W1[tid];
        v1s[tid] = d_v[tid];
        v2s[tid] = d_v[64 + tid];
    }

    int node0 = blockIdx.x * NPB;  // exact: 1250 * 40 = 50000
    for (int i = tid; i < NPB * DIM; i += 256)
        mus[i] = mu[node0 * DIM + i];
    if (tid < NPB) xs[tid] = x[node0 + tid];
    __syncthreads();

    int nl = tid >> 6;   // 0..3 node-in-group
    int o  = tid & 63;   // output feature
    const float4* w3  = (const float4*)(W3s + o * 68);
    const float4* w4c = (const float4*)(W4cs + o * 68);
    float w1 = W1s[o], v1 = v1s[o], v2 = v2s[o];

#pragma unroll 1
    for (int g = 0; g < NPB / 4; g++) {
        int nloc = g * 4 + nl;
        int n = node0 + nloc;
        const float4* m = (const float4*)(mus + nloc * DIM);

        float h = 0.f;
#pragma unroll
        for (int j = 0; j < 16; j++) {
            float4 w = w3[j], mm = m[j];
            h += w.x * mm.x + w.y * mm.y + w.z * mm.z + w.w * mm.w;
        }
        h = fmaxf(h, 0.f);
        hb[g & 1][nl * DIM + o] = h;
        __syncthreads();

        const float4* hv = (const float4*)(hb[g & 1] + nl * DIM);
        float gg = 0.f;
#pragma unroll
        for (int j = 0; j < 16; j++) {
            float4 w = w4c[j], hh = hv[j];
            gg += w.x * hh.x + w.y * hh.y + w.z * hh.z + w.w * hh.w;
        }

        float xv = xs[nloc];
        float xp = fmaxf(xv, 0.f), xn = fmaxf(-xv, 0.f);
        float hx = xp * fmaxf(w1, 0.f) + xn * fmaxf(-w1, 0.f);

        d_hsum[n * DIM + o] = hx + h;
        ((__half*)d_g2h)[n * DIM + o] = __float2half(gg + xp * v1 + xn * v2);
        if (o < REP) { d_cnt[n * REP + o] = 0; d_Sw[n * REP + o] = 0.f; }
    }
}

// ---------------------------------------------------------------------------
// Kernel C: bucket edges by src into privatized replicas. 2 edges/thread with
// vector loads. Per-replica contention = 8 ops/address (was 32).
// ---------------------------------------------------------------------------
__global__ __launch_bounds__(256) void place_kernel(
    const int* __restrict__ ei, const float* __restrict__ ew) {
    int t = blockIdx.x * blockDim.x + threadIdx.x;
    if (t >= NEDGES / 2) return;
    int e = t * 2;
    int2 s2 = *(const int2*)(ei + e);            // src pair
    int2 dd = *(const int2*)(ei + NEDGES + e);   // dst pair
    float2 w2 = *(const float2*)(ew + e);
    int rep = threadIdx.x & (REP - 1);

    int b0 = s2.x * REP + rep;
    int slot0 = atomicAdd(&d_cnt[b0], 1);
    if (slot0 < CAPR) d_rec[b0 * CAPR + slot0] = dd.x;
    atomicAdd(&d_Sw[b0], w2.x);

    int b1 = s2.y * REP + rep;
    int slot1 = atomicAdd(&d_cnt[b1], 1);
    if (slot1 < CAPR) d_rec[b1 * CAPR + slot1] = dd.y;
    atomicAdd(&d_Sw[b1], w2.y);
}

// ---------------------------------------------------------------------------
// Kernel D: pull-based segment sum + fused finalize.
// 8 threads per node; each lane owns 8 features -> one uint4 (16B fp16x8)
// gather per edge. fp32 register accumulation, no atomics.
//   out = relu(hsum + relu(acc + Sw*v3))
// ---------------------------------------------------------------------------
__global__ __launch_bounds__(256) void agg_final_kernel(float* __restrict__ out) {
    int n = blockIdx.x * 32 + (threadIdx.x >> 3);
    if (n >= NNODES) return;
    int q = threadIdx.x & 7;

    int4   c4 = *(const int4*)(d_cnt + n * REP);
    float4 s4 = *(const float4*)(d_Sw + n * REP);
    float sw = (s4.x + s4.y) + (s4.z + s4.w);

    float acc[8];
#pragma unroll
    for (int k = 0; k < 8; k++) acc[k] = 0.f;

#pragma unroll
    for (int r = 0; r < REP; r++) {
        int deg = (r == 0) ? c4.x : (r == 1) ? c4.y : (r == 2) ? c4.z : c4.w;
        deg = min(deg, CAPR);
        const int* recs = d_rec + (n * REP + r) * CAPR;
        int i = 0;
        for (; i + 2 <= deg; i += 2) {
            int r0 = recs[i], r1 = recs[i + 1];
            uint4 u0 = d_g2h[r0 * 8 + q];
            uint4 u1 = d_g2h[r1 * 8 + q];
            float2 f;
            f = __half22float2(*(const __half2*)&u0.x); acc[0] += f.x; acc[1] += f.y;
            f = __half22float2(*(const __half2*)&u0.y); acc[2] += f.x; acc[3] += f.y;
            f = __half22float2(*(const __half2*)&u0.z); acc[4] += f.x; acc[5] += f.y;
            f = __half22float2(*(const __half2*)&u0.w); acc[6] += f.x; acc[7] += f.y;
            f = __half22float2(*(const __half2*)&u1.x); acc[0] += f.x; acc[1] += f.y;
            f = __half22float2(*(const __half2*)&u1.y); acc[2] += f.x; acc[3] += f.y;
            f = __half22float2(*(const __half2*)&u1.z); acc[4] += f.x; acc[5] += f.y;
            f = __half22float2(*(const __half2*)&u1.w); acc[6] += f.x; acc[7] += f.y;
        }
        if (i < deg) {
            uint4 u0 = d_g2h[recs[i] * 8 + q];
            float2 f;
            f = __half22float2(*(const __half2*)&u0.x); acc[0] += f.x; acc[1] += f.y;
            f = __half22float2(*(const __half2*)&u0.y); acc[2] += f.x; acc[3] += f.y;
            f = __half22float2(*(const __half2*)&u0.z); acc[4] += f.x; acc[5] += f.y;
            f = __half22float2(*(const __half2*)&u0.w); acc[6] += f.x; acc[7] += f.y;
        }
    }

    const float4* v3p = (const float4*)(d_v + 128);
    float4 v3a = v3p[q * 2], v3b = v3p[q * 2 + 1];
    float4 ha = ((const float4*)d_hsum)[n * 16 + q * 2];
    float4 hbv = ((const float4*)d_hsum)[n * 16 + q * 2 + 1];

    float4 oa, ob;
    oa.x = fmaxf(ha.x + fmaxf(acc[0] + sw * v3a.x, 0.f), 0.f);
    oa.y = fmaxf(ha.y + fmaxf(acc[1] + sw * v3a.y, 0.f), 0.f);
    oa.z = fmaxf(ha.z + fmaxf(acc[2] + sw * v3a.z, 0.f), 0.f);
    oa.w = fmaxf(ha.w + fmaxf(acc[3] + sw * v3a.w, 0.f), 0.f);
    ob.x = fmaxf(hbv.x + fmaxf(acc[4] + sw * v3b.x, 0.f), 0.f);
    ob.y = fmaxf(hbv.y + fmaxf(acc[5] + sw * v3b.y, 0.f), 0.f);
    ob.z = fmaxf(hbv.z + fmaxf(acc[6] + sw * v3b.z, 0.f), 0.f);
    ob.w = fmaxf(hbv.w + fmaxf(acc[7] + sw * v3b.w, 0.f), 0.f);
    ((float4*)out)[n * 16 + q * 2]     = oa;
    ((float4*)out)[n * 16 + q * 2 + 1] = ob;
}

// ---------------------------------------------------------------------------
extern "C" void kernel_launch(void* const* d_in, const int* in_sizes, int n_in,
                              void* d_out, int out_size) {
    const float* mu = (const float*)d_in[0];
    const float* x  = (const float*)d_in[1];
    const int*   ei = (const int*)d_in[2];
    const float* ew = (const float*)d_in[3];
    const float* W1 = (const float*)d_in[4];
    const float* W2 = (const float*)d_in[5];
    const float* W3 = (const float*)d_in[6];
    const float* W4 = (const float*)d_in[7];

    prep_v_kernel<<<1, 64>>>(W1, W2, W4);
    node_kernel<<<NNODES / NPB, 256>>>(mu, x, W1, W3, W4);
    place_kernel<<<(NEDGES / 2 + 255) / 256, 256>>>(ei, ew);
    agg_final_kernel<<<(NNODES + 31) / 32, 256>>>((float*)d_out);
}

// round 8
// speedup vs baseline: 1.6827x; 1.6827x over previous
#include <cuda_runtime.h>
#include <cuda_fp16.h>

#define NNODES 50000
#define NEDGES 1600000
#define DIM 64
#define CAP 128        // per-node edge bin capacity (deg~Poisson(32))
#define NPB 40         // nodes per block in node_kernel (50000 = 1250 * 40)
#define GRP 10         // nodes per 64-thread group (4 groups * 10 = 40)

// Scratch (allocation-free rule: __device__ globals)
__device__ uint2  d_g2h[NNODES * 16];       // per-node message, fp16x4 per entry [N,64]
__device__ float  d_hsum[NNODES * DIM];     // h_x + h_mu  [N,64]
__device__ float  d_v[3 * DIM];             // v1 | v2 | v3
__device__ float  d_Sw[NNODES];             // scalar segment sum of edge_w
__device__ int    d_cnt[NNODES];            // per-node edge cursor/degree
__device__ int    d_rec[NNODES * CAP];      // dst index per (src, slot)

// ---------------------------------------------------------------------------
// Kernel Z: zero cursors/Sw before the (concurrent) placement pass.
// ---------------------------------------------------------------------------
__global__ void zero_kernel() {
    int t = blockIdx.x * 256 + threadIdx.x;
    if (t < NNODES) { d_cnt[t] = 0; d_Sw[t] = 0.f; }
}

// ---------------------------------------------------------------------------
// Kernel A: v1 = W4a*relu(W1), v2 = W4a*relu(-W1), v3 = W4b*relu(W2).
// ---------------------------------------------------------------------------
__global__ void prep_v_kernel(const float* __restrict__ W1,
                              const float* __restrict__ W2,
                              const float* __restrict__ W4) {
    int o = threadIdx.x;  // 0..63
    float a = 0.f, b = 0.f, c = 0.f;
#pragma unroll
    for (int j = 0; j < DIM; j++) {
        float w4a = W4[o * 192 + j];
        float w4b = W4[o * 192 + 64 + j];
        float w1 = W1[j], w2 = W2[j];
        a += w4a * fmaxf(w1, 0.f);
        b += w4a * fmaxf(-w1, 0.f);
        c += w4b * fmaxf(w2, 0.f);
    }
    d_v[o] = a;
    d_v[64 + o] = b;
    d_v[128 + o] = c;
}

// ---------------------------------------------------------------------------
// Kernel B: per-node precompute, register-resident weights.
// 256 threads = 4 groups x 64; thread (grp,o) keeps W3 row o (16 float4) in
// registers and computes h for its group's 10 nodes via broadcast LDS of mu.
// Then reloads W4c row o into the same regs and computes g from hs.
// Crossbar traffic ~5x lower than the SMEM-weight version; FMA-bound.
// ---------------------------------------------------------------------------
__global__ __launch_bounds__(256) void node_kernel(
    const float* __restrict__ mu, const float* __restrict__ x,
    const float* __restrict__ W1, const float* __restrict__ W3,
    const float* __restrict__ W4) {
    __shared__ float mus[NPB * DIM];    // staged mu rows
    __shared__ float hs[NPB * 68];      // h, padded rows (68 floats)
    __shared__ float xs[NPB];

    int tid = threadIdx.x;
    int node0 = blockIdx.x * NPB;       // exact: 1250 * 40 = 50000
    for (int i = tid; i < NPB * DIM; i += 256)
        mus[i] = mu[node0 * DIM + i];
    if (tid < NPB) xs[tid] = x[node0 + tid];

    int grp = tid >> 6;   // 0..3
    int o   = tid & 63;   // output feature

    // W3 row o -> registers (L2/L1 served; 4-way duplicated across groups)
    float4 wr[16];
    {
        const float4* w3g = (const float4*)(W3 + o * DIM);
#pragma unroll
        for (int j = 0; j < 16; j++) wr[j] = w3g[j];
    }
    __syncthreads();

    // Phase 1: h = relu(mu @ W3^T) for this group's nodes
    const float* mg = mus + grp * GRP * DIM;
#pragma unroll
    for (int n = 0; n < GRP; n++) {
        const float4* m = (const float4*)(mg + n * DIM);
        float h = 0.f;
#pragma unroll
        for (int j = 0; j < 16; j++) {
            float4 w = wr[j], mm = m[j];
            h += w.x * mm.x + w.y * mm.y + w.z * mm.z + w.w * mm.w;
        }
        hs[(grp * GRP + n) * 68 + o] = fmaxf(h, 0.f);
    }

    // W4c row o -> registers (reuses wr)
    {
        const float4* w4g = (const float4*)(W4 + o * 192 + 128);
#pragma unroll
        for (int j = 0; j < 16; j++) wr[j] = w4g[j];
    }
    float w1 = W1[o], v1 = d_v[o], v2 = d_v[64 + o];
    __syncthreads();

    // Phase 2: g = h @ W4c^T ; write hsum and fp16 g2
#pragma unroll
    for (int n = 0; n < GRP; n++) {
        int nn = grp * GRP + n;
        int gn = node0 + nn;
        const float4* hv = (const float4*)(hs + nn * 68);
        float gg = 0.f;
#pragma unroll
        for (int j = 0; j < 16; j++) {
            float4 w = wr[j], hh = hv[j];
            gg += w.x * hh.x + w.y * hh.y + w.z * hh.z + w.w * hh.w;
        }
        float h = hs[nn * 68 + o];
        float xv = xs[nn];
        float xp = fmaxf(xv, 0.f), xn = fmaxf(-xv, 0.f);
        float hx = xp * fmaxf(w1, 0.f) + xn * fmaxf(-w1, 0.f);

        d_hsum[gn * DIM + o] = hx + h;
        ((__half*)d_g2h)[gn * DIM + o] = __float2half(gg + xp * v1 + xn * v2);
    }
}

// ---------------------------------------------------------------------------
// Kernel C: bucket edges by src (R5-proven form). Runs concurrently with
// node_kernel on a side stream (disjoint scratch, disjoint HW resources).
// ---------------------------------------------------------------------------
__global__ __launch_bounds__(256) void place_kernel(
    const int* __restrict__ ei, const float* __restrict__ ew) {
    int e = blockIdx.x * blockDim.x + threadIdx.x;
    if (e >= NEDGES) return;
    int s = ei[e];            // scatter segment
    int d = ei[NEDGES + e];   // gather node
    int slot = atomicAdd(&d_cnt[s], 1);
    if (slot < CAP) d_rec[s * CAP + slot] = d;
    atomicAdd(&d_Sw[s], ew[e]);
}

// ---------------------------------------------------------------------------
// Kernel D: pull-based segment sum + fused finalize (R5-proven form).
// 16 threads per node; fp16x4 (8B) gathers, fp32 accumulation, no atomics.
//   out = relu(hsum + relu(acc + Sw*v3))
// ---------------------------------------------------------------------------
__global__ __launch_bounds__(256) void agg_final_kernel(float* __restrict__ out) {
    int n = blockIdx.x * 16 + (threadIdx.x >> 4);
    int q = threadIdx.x & 15;

    int deg = min(d_cnt[n], CAP);
    const int* recs = d_rec + n * CAP;

    float4 acc = make_float4(0.f, 0.f, 0.f, 0.f);

    int i = 0;
    for (; i + 4 <= deg; i += 4) {
        int r0 = recs[i], r1 = recs[i + 1], r2 = recs[i + 2], r3 = recs[i + 3];
        uint2 u0 = d_g2h[r0 * 16 + q];
        uint2 u1 = d_g2h[r1 * 16 + q];
        uint2 u2 = d_g2h[r2 * 16 + q];
        uint2 u3 = d_g2h[r3 * 16 + q];
        float2 a0 = __half22float2(*(const __half2*)&u0.x);
        float2 b0 = __half22float2(*(const __half2*)&u0.y);
        float2 a1 = __half22float2(*(const __half2*)&u1.x);
        float2 b1 = __half22float2(*(const __half2*)&u1.y);
        float2 a2 = __half22float2(*(const __half2*)&u2.x);
        float2 b2 = __half22float2(*(const __half2*)&u2.y);
        float2 a3 = __half22float2(*(const __half2*)&u3.x);
        float2 b3 = __half22float2(*(const __half2*)&u3.y);
        acc.x += (a0.x + a1.x) + (a2.x + a3.x);
        acc.y += (a0.y + a1.y) + (a2.y + a3.y);
        acc.z += (b0.x + b1.x) + (b2.x + b3.x);
        acc.w += (b0.y + b1.y) + (b2.y + b3.y);
    }
    for (; i < deg; i++) {
        uint2 u0 = d_g2h[recs[i] * 16 + q];
        float2 a0 = __half22float2(*(const __half2*)&u0.x);
        float2 b0 = __half22float2(*(const __half2*)&u0.y);
        acc.x += a0.x; acc.y += a0.y; acc.z += b0.x; acc.w += b0.y;
    }

    float sw = d_Sw[n];
    float4 v3 = ((const float4*)(d_v + 128))[q];
    float4 hsv = ((const float4*)d_hsum)[n * 16 + q];
    float4 o4;
    o4.x = fmaxf(hsv.x + fmaxf(acc.x + sw * v3.x, 0.f), 0.f);
    o4.y = fmaxf(hsv.y + fmaxf(acc.y + sw * v3.y, 0.f), 0.f);
    o4.z = fmaxf(hsv.z + fmaxf(acc.z + sw * v3.z, 0.f), 0.f);
    o4.w = fmaxf(hsv.w + fmaxf(acc.w + sw * v3.w, 0.f), 0.f);
    ((float4*)out)[n * 16 + q] = o4;
}

// ---------------------------------------------------------------------------
// Fork-join: zero -> [ place (side stream) || prep -> node (main) ] -> agg.
// Streams/events created lazily on the first (uncaptured) correctness call;
// the captured graph gets the parallel branch via event dependencies.
// ---------------------------------------------------------------------------
extern "C" void kernel_launch(void* const* d_in, const int* in_sizes, int n_in,
                              void* d_out, int out_size) {
    const float* mu = (const float*)d_in[0];
    const float* x  = (const float*)d_in[1];
    const int*   ei = (const int*)d_in[2];
    const float* ew = (const float*)d_in[3];
    const float* W1 = (const float*)d_in[4];
    const float* W2 = (const float*)d_in[5];
    const float* W3 = (const float*)d_in[6];
    const float* W4 = (const float*)d_in[7];

    static cudaStream_t s_side = nullptr;
    static cudaEvent_t ev_fork, ev_join;
    if (!s_side) {
        cudaStreamCreateWithFlags(&s_side, cudaStreamNonBlocking);
        cudaEventCreateWithFlags(&ev_fork, cudaEventDisableTiming);
        cudaEventCreateWithFlags(&ev_join, cudaEventDisableTiming);
    }

    zero_kernel<<<(NNODES + 255) / 256, 256>>>();
    cudaEventRecord(ev_fork, 0);
    cudaStreamWaitEvent(s_side, ev_fork, 0);

    place_kernel<<<(NEDGES + 255) / 256, 256, 0, s_side>>>(ei, ew);

    prep_v_kernel<<<1, 64>>>(W1, W2, W4);
    node_kernel<<<NNODES / NPB, 256>>>(mu, x, W1, W3, W4);

    cudaEventRecord(ev_join, s_side);
    cudaStreamWaitEvent(0, ev_join, 0);

    agg_final_kernel<<<(NNODES + 15) / 16, 256>>>((float*)d_out);
}